// round 3
// baseline (speedup 1.0000x reference)
#include <cuda_runtime.h>

// Problem: Haar-DWT L1 loss, B=32,C=1,H=512,W=512 fp32 x2 inputs.
// DWT is linear -> butterfly the per-pixel diff. One "quad-pair" = float4 from
// row 2r + float4 below it (both tensors) = 2 Haar blocks.
// N_QUADS = 32*256*128 = 1,048,576. Total blocks = 2,097,152.
#define N_QUADS        1048576
#define N_BLOCKS_TOTAL 2097152.0f

#define CTAS      608              // 152 SMs * 4 CTAs -> exactly one balanced wave
#define THREADS   256
#define STRIDE    (CTAS * THREADS) // 155,648
#define MAX_PAIRS 7                // ceil(N_QUADS / STRIDE); iters 0..5 always valid

__device__ float        g_plo[CTAS];
__device__ float        g_phi[CTAS];
__device__ unsigned int g_count = 0;

__device__ __forceinline__ void load_pair(
    const float4* __restrict__ in, const float4* __restrict__ tgt, int p,
    float4& i0, float4& i1, float4& t0, float4& t1)
{
    // quad p -> row-pair grp = p>>7, col c4 = p&127; base0 = grp*256 + c4
    const int c4    = p & 127;
    const int base0 = 2 * p - c4;
    const int base1 = base0 + 128;
    i0 = __ldcs(&in[base0]);
    i1 = __ldcs(&in[base1]);
    t0 = __ldcs(&tgt[base0]);
    t1 = __ldcs(&tgt[base1]);
}

__device__ __forceinline__ void haar_accum(
    const float4& i0, const float4& i1, const float4& t0, const float4& t1,
    float& lo, float& hi)
{
    // diffs: row0 = (a0,b0,a1,b1), row1 = (c0,d0,c1,d1)
    const float da0 = i0.x - t0.x, db0 = i0.y - t0.y;
    const float da1 = i0.z - t0.z, db1 = i0.w - t0.w;
    const float dc0 = i1.x - t1.x, dd0 = i1.y - t1.y;
    const float dc1 = i1.z - t1.z, dd1 = i1.w - t1.w;

    // Haar butterfly on diff (0.5 folded into final scale):
    // 2*ll = p+q, 2*lh = q-p, 2*hl = -(u+v), 2*hh = u-v
    {
        const float p = da0 + db0, qq = dc0 + dd0;
        const float u = da0 - db0, v  = dc0 - dd0;
        lo += fabsf(p + qq);
        hi += fabsf(qq - p) + fabsf(u + v) + fabsf(u - v);
    }
    {
        const float p = da1 + db1, qq = dc1 + dd1;
        const float u = da1 - db1, v  = dc1 - dd1;
        lo += fabsf(p + qq);
        hi += fabsf(qq - p) + fabsf(u + v) + fabsf(u - v);
    }
}

__device__ __forceinline__ void block_reduce(float& lo, float& hi,
                                             float* slo, float* shi)
{
    #pragma unroll
    for (int o = 16; o > 0; o >>= 1) {
        lo += __shfl_xor_sync(0xffffffffu, lo, o);
        hi += __shfl_xor_sync(0xffffffffu, hi, o);
    }
    const int warp = threadIdx.x >> 5;
    const int lane = threadIdx.x & 31;
    if (lane == 0) { slo[warp] = lo; shi[warp] = hi; }
    __syncthreads();
    if (threadIdx.x < 32) {
        lo = (lane < THREADS / 32) ? slo[lane] : 0.0f;
        hi = (lane < THREADS / 32) ? shi[lane] : 0.0f;
        #pragma unroll
        for (int o = 4; o > 0; o >>= 1) {
            lo += __shfl_xor_sync(0xffffffffu, lo, o);
            hi += __shfl_xor_sync(0xffffffffu, hi, o);
        }
    }
}

__global__ __launch_bounds__(THREADS, 4) void haar_loss_kernel(
    const float4* __restrict__ in,
    const float4* __restrict__ tgt,
    float* __restrict__ out)
{
    const int q0 = blockIdx.x * THREADS + threadIdx.x;

    float lo = 0.0f, hi = 0.0f;

    // 2-deep software pipeline; only the last iteration is predicated
    // (warp-uniform: q0 is contiguous within a warp).
    float4 ci0, ci1, ct0, ct1;
    load_pair(in, tgt, q0, ci0, ci1, ct0, ct1);
    bool vc = true;

    #pragma unroll
    for (int j = 0; j < MAX_PAIRS; j++) {
        const int  qn = q0 + (j + 1) * STRIDE;
        const bool vn = (j + 1 < MAX_PAIRS) && (qn < N_QUADS);
        float4 ni0, ni1, nt0, nt1;
        if (vn) load_pair(in, tgt, qn, ni0, ni1, nt0, nt1);
        if (vc) haar_accum(ci0, ci1, ct0, ct1, lo, hi);
        if (vn) { ci0 = ni0; ci1 = ni1; ct0 = nt0; ct1 = nt1; }
        vc = vn;
    }

    __shared__ float slo[THREADS / 32], shi[THREADS / 32];
    block_reduce(lo, hi, slo, shi);

    // publish per-CTA partial; last CTA to arrive does the final reduction
    __shared__ bool is_last;
    if (threadIdx.x == 0) {
        g_plo[blockIdx.x] = lo;
        g_phi[blockIdx.x] = hi;
        __threadfence();
        const unsigned int c = atomicAdd(&g_count, 1u);
        is_last = (c == CTAS - 1);
    }
    __syncthreads();

    if (is_last) {
        __threadfence();  // acquire: see all CTAs' partials
        float fl = 0.0f, fh = 0.0f;
        for (int i = threadIdx.x; i < CTAS; i += THREADS) {
            fl += g_plo[i];
            fh += g_phi[i];
        }
        __syncthreads();  // reuse of slo/shi
        block_reduce(fl, fh, slo, shi);
        if (threadIdx.x == 0) {
            const float sL = 0.5f / N_BLOCKS_TOTAL;
            const float sH = 0.5f / (3.0f * N_BLOCKS_TOTAL);
            out[0] = fl * sL;
            out[1] = fh * sH;
            g_count = 0;  // reset for next graph replay
        }
    }
}

extern "C" void kernel_launch(void* const* d_in, const int* in_sizes, int n_in,
                              void* d_out, int out_size) {
    const float4* in  = (const float4*)d_in[0];
    const float4* tgt = (const float4*)d_in[1];
    float* out = (float*)d_out;

    haar_loss_kernel<<<CTAS, THREADS>>>(in, tgt, out);
}